// round 15
// baseline (speedup 1.0000x reference)
#include <cuda_runtime.h>
#include <math_constants.h>

#define NROWS 32768
#define C_ENT 1000
#define C_REL 500
#define ROWS_PER_BLK 4
#define NBLK (NROWS / ROWS_PER_BLK)   // 8192
#define NTHR 384
#define L2E 1.4426950408889634f

// scratch (device globals: no allocations allowed)
__device__ float g_partial[NBLK];
__device__ unsigned int g_done;   // zero-init; last block restores to 0 each launch

__device__ __forceinline__ float ex2(float x) {
    float y;
    asm("ex2.approx.ftz.f32 %0, %1;" : "=f"(y) : "f"(x));
    return y;
}

__global__ void __launch_bounds__(NTHR) rank_rows_kernel(
    const float* __restrict__ sub, const float* __restrict__ rel, const float* __restrict__ obj,
    const int* __restrict__ t_sub, const int* __restrict__ t_rel, const int* __restrict__ t_obj,
    float* __restrict__ out)
{
    const int tid  = threadIdx.x;
    const int lane = tid & 31;
    const int w    = tid >> 5;          // 0..11
    const int rloc = w / 3;             // row within block, 0..3
    const int t    = w - rloc * 3;      // tensor 0/1/2
    const int r    = blockIdx.x * ROWS_PER_BLK + rloc;

    const float* base;
    const int*   tptr;
    int nvec;
    if (t == 0)      { base = sub + (size_t)r * C_ENT; nvec = C_ENT / 4; tptr = t_sub; }
    else if (t == 1) { base = rel + (size_t)r * C_REL; nvec = C_REL / 4; tptr = t_rel; }
    else             { base = obj + (size_t)r * C_ENT; nvec = C_ENT / 4; tptr = t_obj; }

    // target-index load first so the dependent gather starts ASAP
    int tgt = 0;
    if (lane == 0) tgt = tptr[r];

    // ---- issue all vector loads (MLP = 8 per lane) ----
    float4 v[8];
    #pragma unroll
    for (int j = 0; j < 8; ++j) {
        const int idx = j * 32 + lane;
        v[j] = (idx < nvec) ? ((const float4*)base)[idx]
                            : make_float4(-CUDART_INF_F, -CUDART_INF_F, -CUDART_INF_F, -CUDART_INF_F);
    }

    // dependent target-logit gather (lane 0 only); overlaps with the reduction
    float xt = 0.f;
    if (lane == 0) xt = base[tgt];

    // ---- per-lane branch-free top-2 (3 FMNMX per value, no index) ----
    float m1 = -CUDART_INF_F, m2 = -CUDART_INF_F;
    #pragma unroll
    for (int j = 0; j < 8; ++j) {
        float lo;
        lo = fminf(m1, v[j].x); m1 = fmaxf(m1, v[j].x); m2 = fmaxf(m2, lo);
        lo = fminf(m1, v[j].y); m1 = fmaxf(m1, v[j].y); m2 = fmaxf(m2, lo);
        lo = fminf(m1, v[j].z); m1 = fmaxf(m1, v[j].z); m2 = fmaxf(m2, lo);
        lo = fminf(m1, v[j].w); m1 = fmaxf(m1, v[j].w); m2 = fmaxf(m2, lo);
    }

    // ---- warp-wide (m1, m2) via xor-butterfly: all lanes converge ----
    #pragma unroll
    for (int off = 16; off > 0; off >>= 1) {
        const float om1 = __shfl_xor_sync(0xffffffffu, m1, off);
        const float om2 = __shfl_xor_sync(0xffffffffu, m2, off);
        const float lo  = fminf(m1, om1);
        m1 = fmaxf(m1, om1);
        m2 = fmaxf(fmaxf(m2, om2), lo);
    }

    // ---- exp-sum relative to the warp-global max: FFMA + MUFU + FADD per value ----
    // padding is -inf -> ex2(-inf) = 0 contributes nothing.
    const float c = -m1 * L2E;
    float s0 = 0.f, s1 = 0.f, s2 = 0.f, s3 = 0.f;
    #pragma unroll
    for (int j = 0; j < 8; ++j) {
        s0 += ex2(fmaf(v[j].x, L2E, c));
        s1 += ex2(fmaf(v[j].y, L2E, c));
        s2 += ex2(fmaf(v[j].z, L2E, c));
        s3 += ex2(fmaf(v[j].w, L2E, c));
    }
    float s = (s0 + s1) + (s2 + s3);
    #pragma unroll
    for (int off = 16; off > 0; off >>= 1)
        s += __shfl_xor_sync(0xffffffffu, s, off);

    // ---- publish per-(row,tensor) stats ----
    __shared__ float s_p0[12], s_p1[12], s_pg[12];
    __shared__ int   s_hit[12];
    __shared__ int   s_last;
    __shared__ float s_red[12];
    if (lane == 0) {
        const float iz = 1.f / s;                 // s == sum exp(x - M1)
        s_p0[w]  = iz;                            // top-1 prob
        s_p1[w]  = ex2((m2 - m1) * L2E) * iz;     // top-2 prob
        s_pg[w]  = ex2((xt - m1) * L2E) * iz;     // target prob
        s_hit[w] = (xt == m1);                    // argmax==target <=> x[target]==max
    }
    __syncthreads();

    if (tid == 0) {
        float total = 0.f;
        #pragma unroll
        for (int rr = 0; rr < ROWS_PER_BLK; ++rr) {
            const int b = rr * 3;
            const float gt   = s_pg[b] * s_pg[b + 1] * s_pg[b + 2];
            const float top1 = s_p0[b] * s_p0[b + 1] * s_p0[b + 2];
            // smallest of the 8 top-2 products is p1*q1*r1; second-smallest is the
            // min over the three single-promotions (partial-order domination).
            const float c1 = s_p0[b] * s_p1[b + 1] * s_p1[b + 2];
            const float c2 = s_p1[b] * s_p0[b + 1] * s_p1[b + 2];
            const float c3 = s_p1[b] * s_p1[b + 1] * s_p0[b + 2];
            const float second = fminf(c1, fminf(c2, c3));
            const bool cond = s_hit[b] && s_hit[b + 1] && s_hit[b + 2];
            const float pre = cond ? second : top1;
            total += fmaxf(0.f, 1.f - gt + pre);
        }
        g_partial[blockIdx.x] = total;
        __threadfence();                          // partial visible before counter bump
        const unsigned int old = atomicAdd(&g_done, 1u);
        s_last = (old == NBLK - 1u);
    }
    __syncthreads();

    // ---- deterministic last-block final reduction (fixed order, fixed tree) ----
    if (s_last) {
        float acc = 0.f;
        #pragma unroll
        for (int j = 0; j < (NBLK / 4) / NTHR; ++j) {           // 2048/384 -> 5 iters w/ guard
            // keep fixed indexing: i = tid + j*NTHR
        }
        // NBLK/4 = 2048 float4; strided fixed-order loop
        for (int i = tid; i < NBLK / 4; i += NTHR) {
            const float4 pv = __ldcg(((const float4*)g_partial) + i);  // L2 read, no stale L1
            acc += (pv.x + pv.y) + (pv.z + pv.w);
        }
        #pragma unroll
        for (int off = 16; off > 0; off >>= 1)
            acc += __shfl_down_sync(0xffffffffu, acc, off);
        if (lane == 0) s_red[w] = acc;
        __syncthreads();
        if (tid == 0) {
            float tot = 0.f;
            #pragma unroll
            for (int ww = 0; ww < 12; ++ww) tot += s_red[ww];
            out[0] = tot * (1.f / (float)NROWS);
            g_done = 0;                            // restore for next graph replay
        }
    }
}

extern "C" void kernel_launch(void* const* d_in, const int* in_sizes, int n_in,
                              void* d_out, int out_size)
{
    const float* sub = (const float*)d_in[0];
    const float* rel = (const float*)d_in[1];
    const float* obj = (const float*)d_in[2];
    const int*   ts  = (const int*)d_in[3];
    const int*   tr  = (const int*)d_in[4];
    const int*   to  = (const int*)d_in[5];
    float* out = (float*)d_out;

    rank_rows_kernel<<<NBLK, NTHR>>>(sub, rel, obj, ts, tr, to, out);
}

// round 16
// speedup vs baseline: 1.1429x; 1.1429x over previous
#include <cuda_runtime.h>
#include <math_constants.h>

#define NROWS 32768
#define C_ENT 1000
#define C_REL 500
#define ROWS_PER_BLK 4
#define NBLK (NROWS / ROWS_PER_BLK)   // 8192
#define NTHR 384
#define L2E 1.4426950408889634f

// per-block partial loss sums (device global: no allocations allowed)
__device__ float g_partial[NBLK];

__device__ __forceinline__ float ex2(float x) {
    float y;
    asm("ex2.approx.ftz.f32 %0, %1;" : "=f"(y) : "f"(x));
    return y;
}

__global__ void __launch_bounds__(NTHR) rank_rows_kernel(
    const float* __restrict__ sub, const float* __restrict__ rel, const float* __restrict__ obj,
    const int* __restrict__ t_sub, const int* __restrict__ t_rel, const int* __restrict__ t_obj)
{
    const int tid  = threadIdx.x;
    const int lane = tid & 31;
    const int w    = tid >> 5;          // 0..11
    const int rloc = w / 3;             // row within block, 0..3
    const int t    = w - rloc * 3;      // tensor 0/1/2
    const int r    = blockIdx.x * ROWS_PER_BLK + rloc;

    const float* base;
    const int*   tptr;
    int nvec;
    if (t == 0)      { base = sub + (size_t)r * C_ENT; nvec = C_ENT / 4; tptr = t_sub; }
    else if (t == 1) { base = rel + (size_t)r * C_REL; nvec = C_REL / 4; tptr = t_rel; }
    else             { base = obj + (size_t)r * C_ENT; nvec = C_ENT / 4; tptr = t_obj; }

    // target-index load first so the dependent gather starts ASAP
    int tgt = 0;
    if (lane == 0) tgt = tptr[r];

    // ---- issue all vector loads (MLP = 8 per lane) ----
    float4 v[8];
    #pragma unroll
    for (int j = 0; j < 8; ++j) {
        const int idx = j * 32 + lane;
        v[j] = (idx < nvec) ? ((const float4*)base)[idx]
                            : make_float4(-CUDART_INF_F, -CUDART_INF_F, -CUDART_INF_F, -CUDART_INF_F);
    }

    // dependent target-logit gather (lane 0 only); overlaps with the reduction
    float xt = 0.f;
    if (lane == 0) xt = base[tgt];

    // ---- per-lane branch-free top-2 (3 FMNMX per value, no index) ----
    float m1 = -CUDART_INF_F, m2 = -CUDART_INF_F;
    #pragma unroll
    for (int j = 0; j < 8; ++j) {
        float lo;
        lo = fminf(m1, v[j].x); m1 = fmaxf(m1, v[j].x); m2 = fmaxf(m2, lo);
        lo = fminf(m1, v[j].y); m1 = fmaxf(m1, v[j].y); m2 = fmaxf(m2, lo);
        lo = fminf(m1, v[j].z); m1 = fmaxf(m1, v[j].z); m2 = fmaxf(m2, lo);
        lo = fminf(m1, v[j].w); m1 = fmaxf(m1, v[j].w); m2 = fmaxf(m2, lo);
    }

    // ---- warp-wide (m1, m2) via xor-butterfly: all lanes converge ----
    #pragma unroll
    for (int off = 16; off > 0; off >>= 1) {
        const float om1 = __shfl_xor_sync(0xffffffffu, m1, off);
        const float om2 = __shfl_xor_sync(0xffffffffu, m2, off);
        const float lo  = fminf(m1, om1);
        m1 = fmaxf(m1, om1);
        m2 = fmaxf(fmaxf(m2, om2), lo);
    }

    // ---- exp-sum relative to the warp-global max: FFMA + MUFU + FADD per value ----
    // padding is -inf -> ex2(-inf) = 0 contributes nothing.
    const float c = -m1 * L2E;
    float s0 = 0.f, s1 = 0.f, s2 = 0.f, s3 = 0.f;
    #pragma unroll
    for (int j = 0; j < 8; ++j) {
        s0 += ex2(fmaf(v[j].x, L2E, c));
        s1 += ex2(fmaf(v[j].y, L2E, c));
        s2 += ex2(fmaf(v[j].z, L2E, c));
        s3 += ex2(fmaf(v[j].w, L2E, c));
    }
    float s = (s0 + s1) + (s2 + s3);
    #pragma unroll
    for (int off = 16; off > 0; off >>= 1)
        s += __shfl_xor_sync(0xffffffffu, s, off);

    // ---- publish per-(row,tensor) stats ----
    __shared__ float s_p0[12], s_p1[12], s_pg[12];
    __shared__ int   s_hit[12];
    if (lane == 0) {
        const float iz = 1.f / s;                 // s == sum exp(x - M1)
        s_p0[w]  = iz;                            // top-1 prob
        s_p1[w]  = ex2((m2 - m1) * L2E) * iz;     // top-2 prob
        s_pg[w]  = ex2((xt - m1) * L2E) * iz;     // target prob
        s_hit[w] = (xt == m1);                    // argmax==target <=> x[target]==max
    }
    __syncthreads();

    if (tid == 0) {
        float total = 0.f;
        #pragma unroll
        for (int rr = 0; rr < ROWS_PER_BLK; ++rr) {
            const int b = rr * 3;
            const float gt   = s_pg[b] * s_pg[b + 1] * s_pg[b + 2];
            const float top1 = s_p0[b] * s_p0[b + 1] * s_p0[b + 2];
            // smallest of the 8 top-2 products is p1*q1*r1; second-smallest is the
            // min over the three single-promotions (partial-order domination).
            const float c1 = s_p0[b] * s_p1[b + 1] * s_p1[b + 2];
            const float c2 = s_p1[b] * s_p0[b + 1] * s_p1[b + 2];
            const float c3 = s_p1[b] * s_p1[b + 1] * s_p0[b + 2];
            const float second = fminf(c1, fminf(c2, c3));
            const bool cond = s_hit[b] && s_hit[b + 1] && s_hit[b + 2];
            const float pre = cond ? second : top1;
            total += fmaxf(0.f, 1.f - gt + pre);
        }
        g_partial[blockIdx.x] = total;
    }
}

__global__ void __launch_bounds__(1024) rank_reduce_kernel(float* __restrict__ out)
{
    // PDL: this kernel is pre-launched while rank_rows_kernel runs; wait for
    // the upstream grid (and its memory) before reading the partials.
    cudaGridDependencySynchronize();

    __shared__ float sm[32];
    const int tid = threadIdx.x;
    const float4* p = (const float4*)g_partial;   // 8192 floats = 2048 float4
    float acc = 0.f;
    #pragma unroll
    for (int j = 0; j < 2; ++j) {
        const float4 v = p[tid + j * 1024];
        acc += (v.x + v.y) + (v.z + v.w);
    }
    #pragma unroll
    for (int off = 16; off > 0; off >>= 1)
        acc += __shfl_down_sync(0xffffffffu, acc, off);
    if ((tid & 31) == 0) sm[tid >> 5] = acc;
    __syncthreads();
    if (tid < 32) {
        acc = sm[tid];
        #pragma unroll
        for (int off = 16; off > 0; off >>= 1)
            acc += __shfl_down_sync(0xffffffffu, acc, off);
        if (tid == 0) out[0] = acc * (1.f / (float)NROWS);
    }
}

extern "C" void kernel_launch(void* const* d_in, const int* in_sizes, int n_in,
                              void* d_out, int out_size)
{
    const float* sub = (const float*)d_in[0];
    const float* rel = (const float*)d_in[1];
    const float* obj = (const float*)d_in[2];
    const int*   ts  = (const int*)d_in[3];
    const int*   tr  = (const int*)d_in[4];
    const int*   to  = (const int*)d_in[5];
    float* out = (float*)d_out;

    rank_rows_kernel<<<NBLK, NTHR>>>(sub, rel, obj, ts, tr, to);

    // Launch the reduction with Programmatic Dependent Launch so its launch
    // latency overlaps the primary kernel's execution.
    cudaLaunchConfig_t cfg = {};
    cfg.gridDim  = dim3(1, 1, 1);
    cfg.blockDim = dim3(1024, 1, 1);
    cfg.dynamicSmemBytes = 0;
    cfg.stream = 0;
    cudaLaunchAttribute attr[1];
    attr[0].id = cudaLaunchAttributeProgrammaticStreamSerialization;
    attr[0].val.programmaticStreamSerializationAllowed = 1;
    cfg.attrs = attr;
    cfg.numAttrs = 1;
    cudaLaunchKernelEx(&cfg, rank_reduce_kernel, out);
}